// round 1
// baseline (speedup 1.0000x reference)
#include <cuda_runtime.h>
#include <cuda_bf16.h>

// Problem constants
#define S_TOT 8192
#define HID   2048
#define NH    16
#define NKV   4
#define DH    128
#define LSEQ  512

// Scratch (allocation-free rule: __device__ globals)
__device__ float g_qkv[S_TOT * 3072];   // [S][ q(2048) | k(512) | v(512) ]
__device__ float g_att[S_TOT * 2048];   // attention output [S][H*D]

__device__ __forceinline__ unsigned f2t(float f) {
    unsigned u;
    asm("cvt.rna.tf32.f32 %0, %1;" : "=r"(u) : "f"(f));
    return u;
}

__device__ __forceinline__ void mma8(float c[4], const unsigned a[4], unsigned b0, unsigned b1) {
    asm volatile(
        "mma.sync.aligned.m16n8k8.row.col.f32.tf32.tf32.f32 "
        "{%0,%1,%2,%3}, {%4,%5,%6,%7}, {%8,%9}, {%0,%1,%2,%3};"
        : "+f"(c[0]), "+f"(c[1]), "+f"(c[2]), "+f"(c[3])
        : "r"(a[0]), "r"(a[1]), "r"(a[2]), "r"(a[3]), "r"(b0), "r"(b1));
}

// ---------------------------------------------------------------------------
// Generic tf32 GEMM: C[m][n] = sum_k A[row(m)][k] * W[n][k] + bias[n]
// A rows:   a_off + m*a_stride   (lda = 2048 fixed, K = 2048 fixed)
// C rows:   c_off + m*c_stride   (ldc variable)
// Block tile 128x128x32, 8 warps of 64x32. Grid: (N/128, M/128).
// ---------------------------------------------------------------------------
__global__ __launch_bounds__(256, 2) void gemm_tf32(
    const float* __restrict__ A, int a_off, int a_stride,
    const float* __restrict__ W, const float* __restrict__ bias,
    float* __restrict__ C, int ldc, int c_off, int c_stride)
{
    __shared__ unsigned sA[128 * 36];   // stride 36 -> bank = 4*row+col (conflict-free frags)
    __shared__ unsigned sB[128 * 36];

    const int tid = threadIdx.x;
    const int wid = tid >> 5, lane = tid & 31;
    const int gid = lane >> 2, tig = lane & 3;
    const int wm = (wid >> 2) * 64, wn = (wid & 3) * 32;
    const int bm = blockIdx.y * 128, bn = blockIdx.x * 128;

    float acc[4][4][4];
#pragma unroll
    for (int i = 0; i < 4; i++)
#pragma unroll
        for (int j = 0; j < 4; j++)
#pragma unroll
            for (int c = 0; c < 4; c++) acc[i][j][c] = 0.f;

    const int lr = tid >> 3;        // 0..31
    const int lc = (tid & 7) * 4;   // 0..28

#pragma unroll 1
    for (int kt = 0; kt < 2048; kt += 32) {
        __syncthreads();
#pragma unroll
        for (int i = 0; i < 4; i++) {
            int r = i * 32 + lr;
            float4 av = *(const float4*)(A + (size_t)(a_off + (bm + r) * a_stride) * 2048 + kt + lc);
            unsigned* d = &sA[r * 36 + lc];
            d[0] = f2t(av.x); d[1] = f2t(av.y); d[2] = f2t(av.z); d[3] = f2t(av.w);
            float4 bv = *(const float4*)(W + (size_t)(bn + r) * 2048 + kt + lc);
            unsigned* e = &sB[r * 36 + lc];
            e[0] = f2t(bv.x); e[1] = f2t(bv.y); e[2] = f2t(bv.z); e[3] = f2t(bv.w);
        }
        __syncthreads();
#pragma unroll
        for (int ks = 0; ks < 4; ks++) {
            unsigned af[4][4], bf[4][2];
#pragma unroll
            for (int mf = 0; mf < 4; mf++) {
                const unsigned* p = &sA[(wm + mf * 16 + gid) * 36 + ks * 8 + tig];
                af[mf][0] = p[0];      af[mf][2] = p[4];
                af[mf][1] = p[8 * 36]; af[mf][3] = p[8 * 36 + 4];
            }
#pragma unroll
            for (int nf = 0; nf < 4; nf++) {
                const unsigned* p = &sB[(wn + nf * 8 + gid) * 36 + ks * 8 + tig];
                bf[nf][0] = p[0]; bf[nf][1] = p[4];
            }
#pragma unroll
            for (int mf = 0; mf < 4; mf++)
#pragma unroll
                for (int nf = 0; nf < 4; nf++)
                    mma8(acc[mf][nf], af[mf], bf[nf][0], bf[nf][1]);
        }
    }

#pragma unroll
    for (int mf = 0; mf < 4; mf++) {
#pragma unroll
        for (int nf = 0; nf < 4; nf++) {
            int gc = bn + wn + nf * 8 + tig * 2;
            float b0 = bias ? bias[gc] : 0.f;
            float b1 = bias ? bias[gc + 1] : 0.f;
            int gr = bm + wm + mf * 16 + gid;
            float2 v0 = make_float2(acc[mf][nf][0] + b0, acc[mf][nf][1] + b1);
            float2 v1 = make_float2(acc[mf][nf][2] + b0, acc[mf][nf][3] + b1);
            *(float2*)&C[(size_t)(c_off + gr * c_stride) * ldc + gc] = v0;
            *(float2*)&C[(size_t)(c_off + (gr + 8) * c_stride) * ldc + gc] = v1;
        }
    }
}

// ---------------------------------------------------------------------------
// Per-head RMSNorm + RoPE, in-place on g_qkv (q heads 0..15, k heads 0..3).
// One warp per (token, head). Even tokens = und weights, odd = gen weights.
// ---------------------------------------------------------------------------
__global__ __launch_bounds__(256) void norm_rope(
    float* __restrict__ qkv,
    const float* __restrict__ cosp, const float* __restrict__ sinp,
    const float* __restrict__ qn, const float* __restrict__ qng,
    const float* __restrict__ kn, const float* __restrict__ kng)
{
    int task = blockIdx.x * 8 + (threadIdx.x >> 5);
    int lane = threadIdx.x & 31;
    int s = task / 20, j = task % 20;
    bool und = (s & 1) == 0;
    const float* w;
    int off;
    if (j < 16) { off = j * 128;               w = und ? qn : qng; }
    else        { off = 2048 + (j - 16) * 128; w = und ? kn : kng; }

    float* p = qkv + (size_t)s * 3072 + off;
    float x0 = p[lane], x1 = p[lane + 32], x2 = p[lane + 64], x3 = p[lane + 96];
    float ss = x0 * x0 + x1 * x1 + x2 * x2 + x3 * x3;
#pragma unroll
    for (int d = 16; d; d >>= 1) ss += __shfl_xor_sync(0xffffffffu, ss, d);
    float r = rsqrtf(ss * (1.0f / 128.0f) + 1e-6f);
    x0 = x0 * r * w[lane];      x1 = x1 * r * w[lane + 32];
    x2 = x2 * r * w[lane + 64]; x3 = x3 * r * w[lane + 96];

    const float* cs = cosp + (size_t)s * 128;
    const float* sn = sinp + (size_t)s * 128;
    float c0 = cs[lane], c1 = cs[lane + 32], c2 = cs[lane + 64], c3 = cs[lane + 96];
    float s0 = sn[lane], s1 = sn[lane + 32], s2 = sn[lane + 64], s3 = sn[lane + 96];

    p[lane]      = x0 * c0 - x2 * s0;
    p[lane + 32] = x1 * c1 - x3 * s1;
    p[lane + 64] = x2 * c2 + x0 * s2;
    p[lane + 96] = x3 * c3 + x1 * s3;
}

// ---------------------------------------------------------------------------
// Causal GQA flash attention (tf32 mma). Block = (b, hkv, 32 q-rows) covering
// all G=4 grouped q-heads (K/V tiles shared). 8 warps, each owns 16 q-rows of
// one head. K-tile = 64 keys.
// ---------------------------------------------------------------------------
#define SK_STR 132   // 132 % 32 == 4 -> conflict-free QK B-frags
#define SV_STR 136   // 136 % 32 == 8 -> conflict-free PV B-frags
#define SP_STR 68    //  68 % 32 == 4 -> conflict-free PV A-frags
#define ATT_SMEM ((64 * SK_STR + 64 * SV_STR + 8 * 16 * SP_STR) * 4)

__global__ __launch_bounds__(256, 1) void attn_kernel(
    const float* __restrict__ qkv, float* __restrict__ outp)
{
    extern __shared__ unsigned sm[];
    unsigned* sK = sm;
    unsigned* sV = sm + 64 * SK_STR;
    float* sP = (float*)(sm + 64 * SK_STR + 64 * SV_STR);

    const int qt = blockIdx.x, hkv = blockIdx.y, b = blockIdx.z;
    const int tid = threadIdx.x, wid = tid >> 5, lane = tid & 31;
    const int gid = lane >> 2, tig = lane & 3;
    const int g = wid >> 1;
    const int h = hkv * 4 + g;
    const int q0 = qt * 32;
    const int qrow = q0 + (wid & 1) * 16 + gid;
    const int trow = b * 512 + qrow;
    const float scale = 0.08838834764831845f;  // 1/sqrt(128), folded into Q

    unsigned qa[16][4];
    {
        const float* qp  = qkv + (size_t)trow * 3072 + h * 128;
        const float* qp8 = qp + 8 * 3072;
#pragma unroll
        for (int kf = 0; kf < 16; kf++) {
            qa[kf][0] = f2t(qp [kf * 8 + tig]     * scale);
            qa[kf][2] = f2t(qp [kf * 8 + tig + 4] * scale);
            qa[kf][1] = f2t(qp8[kf * 8 + tig]     * scale);
            qa[kf][3] = f2t(qp8[kf * 8 + tig + 4] * scale);
        }
    }

    float o[16][4];
#pragma unroll
    for (int i = 0; i < 16; i++)
#pragma unroll
        for (int c = 0; c < 4; c++) o[i][c] = 0.f;
    float m0 = -1e30f, m1 = -1e30f, l0 = 0.f, l1 = 0.f;
    float* myP = sP + wid * 16 * SP_STR;
    const int ntiles = (q0 >> 6) + 1;

#pragma unroll 1
    for (int j = 0; j < ntiles; j++) {
        int c0 = j * 64;
        __syncthreads();
        {
            const float* kb = qkv + (size_t)(b * 512 + c0) * 3072 + 2048 + hkv * 128;
            const float* vb = kb + 512;
#pragma unroll
            for (int i = 0; i < 8; i++) {
                int r = i * 8 + wid;
                int cc = lane * 4;
                float4 kv = *(const float4*)(kb + (size_t)r * 3072 + cc);
                unsigned* d = &sK[r * SK_STR + cc];
                d[0] = f2t(kv.x); d[1] = f2t(kv.y); d[2] = f2t(kv.z); d[3] = f2t(kv.w);
                float4 vv = *(const float4*)(vb + (size_t)r * 3072 + cc);
                unsigned* e = &sV[r * SV_STR + cc];
                e[0] = f2t(vv.x); e[1] = f2t(vv.y); e[2] = f2t(vv.z); e[3] = f2t(vv.w);
            }
        }
        __syncthreads();

        float s[8][4];
#pragma unroll
        for (int nf = 0; nf < 8; nf++)
#pragma unroll
            for (int c = 0; c < 4; c++) s[nf][c] = 0.f;

#pragma unroll
        for (int kf = 0; kf < 16; kf++) {
#pragma unroll
            for (int nf = 0; nf < 8; nf++) {
                unsigned b0 = sK[(nf * 8 + gid) * SK_STR + kf * 8 + tig];
                unsigned b1 = sK[(nf * 8 + gid) * SK_STR + kf * 8 + tig + 4];
                mma8(s[nf], qa[kf], b0, b1);
            }
        }

        if (j == ntiles - 1) {
#pragma unroll
            for (int nf = 0; nf < 8; nf++) {
                int col = c0 + nf * 8 + tig * 2;
                if (col     > qrow)     s[nf][0] = -1e30f;
                if (col + 1 > qrow)     s[nf][1] = -1e30f;
                if (col     > qrow + 8) s[nf][2] = -1e30f;
                if (col + 1 > qrow + 8) s[nf][3] = -1e30f;
            }
        }

        float mj0 = -1e30f, mj1 = -1e30f;
#pragma unroll
        for (int nf = 0; nf < 8; nf++) {
            mj0 = fmaxf(mj0, fmaxf(s[nf][0], s[nf][1]));
            mj1 = fmaxf(mj1, fmaxf(s[nf][2], s[nf][3]));
        }
        mj0 = fmaxf(mj0, __shfl_xor_sync(0xffffffffu, mj0, 1));
        mj0 = fmaxf(mj0, __shfl_xor_sync(0xffffffffu, mj0, 2));
        mj1 = fmaxf(mj1, __shfl_xor_sync(0xffffffffu, mj1, 1));
        mj1 = fmaxf(mj1, __shfl_xor_sync(0xffffffffu, mj1, 2));

        float mn0 = fmaxf(m0, mj0), mn1 = fmaxf(m1, mj1);
        float f0 = __expf(m0 - mn0), f1 = __expf(m1 - mn1);
        m0 = mn0; m1 = mn1;
        l0 *= f0; l1 *= f1;
#pragma unroll
        for (int nf = 0; nf < 16; nf++) {
            o[nf][0] *= f0; o[nf][1] *= f0;
            o[nf][2] *= f1; o[nf][3] *= f1;
        }
#pragma unroll
        for (int nf = 0; nf < 8; nf++) {
            float p0 = __expf(s[nf][0] - m0), p1 = __expf(s[nf][1] - m0);
            float p2 = __expf(s[nf][2] - m1), p3 = __expf(s[nf][3] - m1);
            l0 += p0 + p1; l1 += p2 + p3;
            *(float2*)&myP[gid * SP_STR + nf * 8 + tig * 2]       = make_float2(p0, p1);
            *(float2*)&myP[(gid + 8) * SP_STR + nf * 8 + tig * 2] = make_float2(p2, p3);
        }
        __syncwarp();
#pragma unroll
        for (int kf = 0; kf < 8; kf++) {
            unsigned a[4];
            a[0] = f2t(myP[gid * SP_STR + kf * 8 + tig]);
            a[2] = f2t(myP[gid * SP_STR + kf * 8 + tig + 4]);
            a[1] = f2t(myP[(gid + 8) * SP_STR + kf * 8 + tig]);
            a[3] = f2t(myP[(gid + 8) * SP_STR + kf * 8 + tig + 4]);
#pragma unroll
            for (int nf = 0; nf < 16; nf++) {
                unsigned b0 = sV[(kf * 8 + tig) * SV_STR + nf * 8 + gid];
                unsigned b1 = sV[(kf * 8 + tig + 4) * SV_STR + nf * 8 + gid];
                mma8(o[nf], a, b0, b1);
            }
        }
        __syncwarp();
    }

    float L0 = l0 + __shfl_xor_sync(0xffffffffu, l0, 1);
    L0 += __shfl_xor_sync(0xffffffffu, L0, 2);
    float L1 = l1 + __shfl_xor_sync(0xffffffffu, l1, 1);
    L1 += __shfl_xor_sync(0xffffffffu, L1, 2);
    float inv0 = 1.f / L0, inv1 = 1.f / L1;

    float* op  = outp + (size_t)trow * 2048 + h * 128;
    float* op8 = op + 8 * 2048;
#pragma unroll
    for (int nf = 0; nf < 16; nf++) {
        int d = nf * 8 + tig * 2;
        *(float2*)&op[d]  = make_float2(o[nf][0] * inv0, o[nf][1] * inv0);
        *(float2*)&op8[d] = make_float2(o[nf][2] * inv1, o[nf][3] * inv1);
    }
}

// ---------------------------------------------------------------------------
extern "C" void kernel_launch(void* const* d_in, const int* in_sizes, int n_in,
                              void* d_out, int out_size)
{
    const float* und  = (const float*)d_in[0];
    const float* gen  = (const float*)d_in[1];
    // d_in[2], d_in[3]: und/gen token index arrays (arange(0,S,2)/arange(1,S,2) by construction)
    const float* q_w  = (const float*)d_in[4];
    const float* q_b  = (const float*)d_in[5];
    const float* k_w  = (const float*)d_in[6];
    const float* k_b  = (const float*)d_in[7];
    const float* v_w  = (const float*)d_in[8];
    const float* v_b  = (const float*)d_in[9];
    const float* o_w  = (const float*)d_in[10];
    const float* q_wg = (const float*)d_in[11];
    const float* q_bg = (const float*)d_in[12];
    const float* k_wg = (const float*)d_in[13];
    const float* k_bg = (const float*)d_in[14];
    const float* v_wg = (const float*)d_in[15];
    const float* v_bg = (const float*)d_in[16];
    const float* o_wg = (const float*)d_in[17];
    const float* qn   = (const float*)d_in[18];
    const float* kn   = (const float*)d_in[19];
    const float* qng  = (const float*)d_in[20];
    const float* kng  = (const float*)d_in[21];
    const float* cosp = (const float*)d_in[22];
    const float* sinp = (const float*)d_in[23];
    float* out = (float*)d_out;

    float *qkv = nullptr, *att = nullptr;
    cudaGetSymbolAddress((void**)&qkv, g_qkv);
    cudaGetSymbolAddress((void**)&att, g_att);

    dim3 blk(256);

    // QKV projections: und rows -> even tokens (c_off=0), gen rows -> odd (c_off=1)
    gemm_tf32<<<dim3(16, 32), blk>>>(und, 0, 1, q_w,  q_b,  qkv,        3072, 0, 2);
    gemm_tf32<<<dim3(4, 32),  blk>>>(und, 0, 1, k_w,  k_b,  qkv + 2048, 3072, 0, 2);
    gemm_tf32<<<dim3(4, 32),  blk>>>(und, 0, 1, v_w,  v_b,  qkv + 2560, 3072, 0, 2);
    gemm_tf32<<<dim3(16, 32), blk>>>(gen, 0, 1, q_wg, q_bg, qkv,        3072, 1, 2);
    gemm_tf32<<<dim3(4, 32),  blk>>>(gen, 0, 1, k_wg, k_bg, qkv + 2048, 3072, 1, 2);
    gemm_tf32<<<dim3(4, 32),  blk>>>(gen, 0, 1, v_wg, v_bg, qkv + 2560, 3072, 1, 2);

    // RMSNorm + RoPE on q and k heads, in place
    norm_rope<<<20480, 256>>>(qkv, cosp, sinp, qn, qng, kn, kng);

    // Flash attention
    cudaFuncSetAttribute(attn_kernel, cudaFuncAttributeMaxDynamicSharedMemorySize, ATT_SMEM);
    attn_kernel<<<dim3(16, 4, 16), 256, ATT_SMEM>>>(qkv, att);

    // Output projections: even tokens -> out_und, odd -> out_gen
    gemm_tf32<<<dim3(16, 32), blk>>>(att, 0, 2, o_w,  nullptr, out,                2048, 0, 1);
    gemm_tf32<<<dim3(16, 32), blk>>>(att, 1, 2, o_wg, nullptr, out + 4096 * 2048, 2048, 0, 1);
}

// round 2
// speedup vs baseline: 1.0058x; 1.0058x over previous
#include <cuda_runtime.h>
#include <cuda_bf16.h>

// Problem constants
#define S_TOT 8192
#define HID   2048
#define NH    16
#define NKV   4
#define DH    128
#define LSEQ  512

// Scratch (allocation-free rule: __device__ globals)
__device__ float g_qkv[S_TOT * 3072];   // [S][ q(2048) | k(512) | v(512) ]
__device__ float g_att[S_TOT * 2048];   // attention output [S][H*D]

__device__ __forceinline__ unsigned f2t(float f) {
    unsigned u;
    asm("cvt.rna.tf32.f32 %0, %1;" : "=r"(u) : "f"(f));
    return u;
}

__device__ __forceinline__ void mma8(float c[4], const unsigned a[4], unsigned b0, unsigned b1) {
    asm volatile(
        "mma.sync.aligned.m16n8k8.row.col.f32.tf32.tf32.f32 "
        "{%0,%1,%2,%3}, {%4,%5,%6,%7}, {%8,%9}, {%0,%1,%2,%3};"
        : "+f"(c[0]), "+f"(c[1]), "+f"(c[2]), "+f"(c[3])
        : "r"(a[0]), "r"(a[1]), "r"(a[2]), "r"(a[3]), "r"(b0), "r"(b1));
}

// ---------------------------------------------------------------------------
// Generic tf32 GEMM: C[m][n] = sum_k A[row(m)][k] * W[n][k] + bias[n]
// A rows:   a_off + m*a_stride   (lda = 2048 fixed, K = 2048 fixed)
// C rows:   c_off + m*c_stride   (ldc variable)
// Block tile 128x128x32, 8 warps of 64x32. Grid: (N/128, M/128).
// ---------------------------------------------------------------------------
__global__ __launch_bounds__(256, 2) void gemm_tf32(
    const float* __restrict__ A, int a_off, int a_stride,
    const float* __restrict__ W, const float* __restrict__ bias,
    float* __restrict__ C, int ldc, int c_off, int c_stride)
{
    __shared__ unsigned sA[128 * 36];   // stride 36 -> bank = 4*row+col (conflict-free frags)
    __shared__ unsigned sB[128 * 36];

    const int tid = threadIdx.x;
    const int wid = tid >> 5, lane = tid & 31;
    const int gid = lane >> 2, tig = lane & 3;
    const int wm = (wid >> 2) * 64, wn = (wid & 3) * 32;
    const int bm = blockIdx.y * 128, bn = blockIdx.x * 128;

    float acc[4][4][4];
#pragma unroll
    for (int i = 0; i < 4; i++)
#pragma unroll
        for (int j = 0; j < 4; j++)
#pragma unroll
            for (int c = 0; c < 4; c++) acc[i][j][c] = 0.f;

    const int lr = tid >> 3;        // 0..31
    const int lc = (tid & 7) * 4;   // 0..28

#pragma unroll 1
    for (int kt = 0; kt < 2048; kt += 32) {
        __syncthreads();
#pragma unroll
        for (int i = 0; i < 4; i++) {
            int r = i * 32 + lr;
            float4 av = *(const float4*)(A + (size_t)(a_off + (bm + r) * a_stride) * 2048 + kt + lc);
            unsigned* d = &sA[r * 36 + lc];
            d[0] = f2t(av.x); d[1] = f2t(av.y); d[2] = f2t(av.z); d[3] = f2t(av.w);
            float4 bv = *(const float4*)(W + (size_t)(bn + r) * 2048 + kt + lc);
            unsigned* e = &sB[r * 36 + lc];
            e[0] = f2t(bv.x); e[1] = f2t(bv.y); e[2] = f2t(bv.z); e[3] = f2t(bv.w);
        }
        __syncthreads();
#pragma unroll
        for (int ks = 0; ks < 4; ks++) {
            unsigned af[4][4], bf[4][2];
#pragma unroll
            for (int mf = 0; mf < 4; mf++) {
                const unsigned* p = &sA[(wm + mf * 16 + gid) * 36 + ks * 8 + tig];
                af[mf][0] = p[0];      af[mf][2] = p[4];
                af[mf][1] = p[8 * 36]; af[mf][3] = p[8 * 36 + 4];
            }
#pragma unroll
            for (int nf = 0; nf < 4; nf++) {
                const unsigned* p = &sB[(wn + nf * 8 + gid) * 36 + ks * 8 + tig];
                bf[nf][0] = p[0]; bf[nf][1] = p[4];
            }
#pragma unroll
            for (int mf = 0; mf < 4; mf++)
#pragma unroll
                for (int nf = 0; nf < 4; nf++)
                    mma8(acc[mf][nf], af[mf], bf[nf][0], bf[nf][1]);
        }
    }

#pragma unroll
    for (int mf = 0; mf < 4; mf++) {
#pragma unroll
        for (int nf = 0; nf < 4; nf++) {
            int gc = bn + wn + nf * 8 + tig * 2;
            float b0 = bias ? bias[gc] : 0.f;
            float b1 = bias ? bias[gc + 1] : 0.f;
            int gr = bm + wm + mf * 16 + gid;
            float2 v0 = make_float2(acc[mf][nf][0] + b0, acc[mf][nf][1] + b1);
            float2 v1 = make_float2(acc[mf][nf][2] + b0, acc[mf][nf][3] + b1);
            *(float2*)&C[(size_t)(c_off + gr * c_stride) * ldc + gc] = v0;
            *(float2*)&C[(size_t)(c_off + (gr + 8) * c_stride) * ldc + gc] = v1;
        }
    }
}

// ---------------------------------------------------------------------------
// Per-head RMSNorm + RoPE, in-place on g_qkv (q heads 0..15, k heads 0..3).
// One warp per (token, head). Even tokens = und weights, odd = gen weights.
// ---------------------------------------------------------------------------
__global__ __launch_bounds__(256) void norm_rope(
    float* __restrict__ qkv,
    const float* __restrict__ cosp, const float* __restrict__ sinp,
    const float* __restrict__ qn, const float* __restrict__ qng,
    const float* __restrict__ kn, const float* __restrict__ kng)
{
    int task = blockIdx.x * 8 + (threadIdx.x >> 5);
    int lane = threadIdx.x & 31;
    int s = task / 20, j = task % 20;
    bool und = (s & 1) == 0;
    const float* w;
    int off;
    if (j < 16) { off = j * 128;               w = und ? qn : qng; }
    else        { off = 2048 + (j - 16) * 128; w = und ? kn : kng; }

    float* p = qkv + (size_t)s * 3072 + off;
    float x0 = p[lane], x1 = p[lane + 32], x2 = p[lane + 64], x3 = p[lane + 96];
    float ss = x0 * x0 + x1 * x1 + x2 * x2 + x3 * x3;
#pragma unroll
    for (int d = 16; d; d >>= 1) ss += __shfl_xor_sync(0xffffffffu, ss, d);
    float r = rsqrtf(ss * (1.0f / 128.0f) + 1e-6f);
    x0 = x0 * r * w[lane];      x1 = x1 * r * w[lane + 32];
    x2 = x2 * r * w[lane + 64]; x3 = x3 * r * w[lane + 96];

    const float* cs = cosp + (size_t)s * 128;
    const float* sn = sinp + (size_t)s * 128;
    float c0 = cs[lane], c1 = cs[lane + 32], c2 = cs[lane + 64], c3 = cs[lane + 96];
    float s0 = sn[lane], s1 = sn[lane + 32], s2 = sn[lane + 64], s3 = sn[lane + 96];

    p[lane]      = x0 * c0 - x2 * s0;
    p[lane + 32] = x1 * c1 - x3 * s1;
    p[lane + 64] = x2 * c2 + x0 * s2;
    p[lane + 96] = x3 * c3 + x1 * s3;
}

// ---------------------------------------------------------------------------
// Causal GQA flash attention (tf32 mma). Block = (b, hkv, 32 q-rows) covering
// all G=4 grouped q-heads (K/V tiles shared). 8 warps, each owns 16 q-rows of
// one head. K-tile = 64 keys.
// ---------------------------------------------------------------------------
#define SK_STR 132   // 132 % 32 == 4 -> conflict-free QK B-frags
#define SV_STR 136   // 136 % 32 == 8 -> conflict-free PV B-frags
#define SP_STR 68    //  68 % 32 == 4 -> conflict-free PV A-frags
#define ATT_SMEM ((64 * SK_STR + 64 * SV_STR + 8 * 16 * SP_STR) * 4)

__global__ __launch_bounds__(256, 1) void attn_kernel(
    const float* __restrict__ qkv, float* __restrict__ outp)
{
    extern __shared__ unsigned sm[];
    unsigned* sK = sm;
    unsigned* sV = sm + 64 * SK_STR;
    float* sP = (float*)(sm + 64 * SK_STR + 64 * SV_STR);

    const int qt = blockIdx.x, hkv = blockIdx.y, b = blockIdx.z;
    const int tid = threadIdx.x, wid = tid >> 5, lane = tid & 31;
    const int gid = lane >> 2, tig = lane & 3;
    const int g = wid >> 1;
    const int h = hkv * 4 + g;
    const int q0 = qt * 32;
    const int qrow = q0 + (wid & 1) * 16 + gid;
    const int trow = b * 512 + qrow;
    const float scale = 0.08838834764831845f;  // 1/sqrt(128), folded into Q

    unsigned qa[16][4];
    {
        const float* qp  = qkv + (size_t)trow * 3072 + h * 128;
        const float* qp8 = qp + 8 * 3072;
#pragma unroll
        for (int kf = 0; kf < 16; kf++) {
            qa[kf][0] = f2t(qp [kf * 8 + tig]     * scale);
            qa[kf][2] = f2t(qp [kf * 8 + tig + 4] * scale);
            qa[kf][1] = f2t(qp8[kf * 8 + tig]     * scale);
            qa[kf][3] = f2t(qp8[kf * 8 + tig + 4] * scale);
        }
    }

    float o[16][4];
#pragma unroll
    for (int i = 0; i < 16; i++)
#pragma unroll
        for (int c = 0; c < 4; c++) o[i][c] = 0.f;
    float m0 = -1e30f, m1 = -1e30f, l0 = 0.f, l1 = 0.f;
    float* myP = sP + wid * 16 * SP_STR;
    const int ntiles = (q0 >> 6) + 1;

#pragma unroll 1
    for (int j = 0; j < ntiles; j++) {
        int c0 = j * 64;
        __syncthreads();
        {
            const float* kb = qkv + (size_t)(b * 512 + c0) * 3072 + 2048 + hkv * 128;
            const float* vb = kb + 512;
#pragma unroll
            for (int i = 0; i < 8; i++) {
                int r = i * 8 + wid;
                int cc = lane * 4;
                float4 kv = *(const float4*)(kb + (size_t)r * 3072 + cc);
                unsigned* d = &sK[r * SK_STR + cc];
                d[0] = f2t(kv.x); d[1] = f2t(kv.y); d[2] = f2t(kv.z); d[3] = f2t(kv.w);
                float4 vv = *(const float4*)(vb + (size_t)r * 3072 + cc);
                unsigned* e = &sV[r * SV_STR + cc];
                e[0] = f2t(vv.x); e[1] = f2t(vv.y); e[2] = f2t(vv.z); e[3] = f2t(vv.w);
            }
        }
        __syncthreads();

        float s[8][4];
#pragma unroll
        for (int nf = 0; nf < 8; nf++)
#pragma unroll
            for (int c = 0; c < 4; c++) s[nf][c] = 0.f;

#pragma unroll
        for (int kf = 0; kf < 16; kf++) {
#pragma unroll
            for (int nf = 0; nf < 8; nf++) {
                unsigned b0 = sK[(nf * 8 + gid) * SK_STR + kf * 8 + tig];
                unsigned b1 = sK[(nf * 8 + gid) * SK_STR + kf * 8 + tig + 4];
                mma8(s[nf], qa[kf], b0, b1);
            }
        }

        if (j == ntiles - 1) {
#pragma unroll
            for (int nf = 0; nf < 8; nf++) {
                int col = c0 + nf * 8 + tig * 2;
                if (col     > qrow)     s[nf][0] = -1e30f;
                if (col + 1 > qrow)     s[nf][1] = -1e30f;
                if (col     > qrow + 8) s[nf][2] = -1e30f;
                if (col + 1 > qrow + 8) s[nf][3] = -1e30f;
            }
        }

        float mj0 = -1e30f, mj1 = -1e30f;
#pragma unroll
        for (int nf = 0; nf < 8; nf++) {
            mj0 = fmaxf(mj0, fmaxf(s[nf][0], s[nf][1]));
            mj1 = fmaxf(mj1, fmaxf(s[nf][2], s[nf][3]));
        }
        mj0 = fmaxf(mj0, __shfl_xor_sync(0xffffffffu, mj0, 1));
        mj0 = fmaxf(mj0, __shfl_xor_sync(0xffffffffu, mj0, 2));
        mj1 = fmaxf(mj1, __shfl_xor_sync(0xffffffffu, mj1, 1));
        mj1 = fmaxf(mj1, __shfl_xor_sync(0xffffffffu, mj1, 2));

        float mn0 = fmaxf(m0, mj0), mn1 = fmaxf(m1, mj1);
        float f0 = __expf(m0 - mn0), f1 = __expf(m1 - mn1);
        m0 = mn0; m1 = mn1;
        l0 *= f0; l1 *= f1;
#pragma unroll
        for (int nf = 0; nf < 16; nf++) {
            o[nf][0] *= f0; o[nf][1] *= f0;
            o[nf][2] *= f1; o[nf][3] *= f1;
        }
#pragma unroll
        for (int nf = 0; nf < 8; nf++) {
            float p0 = __expf(s[nf][0] - m0), p1 = __expf(s[nf][1] - m0);
            float p2 = __expf(s[nf][2] - m1), p3 = __expf(s[nf][3] - m1);
            l0 += p0 + p1; l1 += p2 + p3;
            *(float2*)&myP[gid * SP_STR + nf * 8 + tig * 2]       = make_float2(p0, p1);
            *(float2*)&myP[(gid + 8) * SP_STR + nf * 8 + tig * 2] = make_float2(p2, p3);
        }
        __syncwarp();
#pragma unroll
        for (int kf = 0; kf < 8; kf++) {
            unsigned a[4];
            a[0] = f2t(myP[gid * SP_STR + kf * 8 + tig]);
            a[2] = f2t(myP[gid * SP_STR + kf * 8 + tig + 4]);
            a[1] = f2t(myP[(gid + 8) * SP_STR + kf * 8 + tig]);
            a[3] = f2t(myP[(gid + 8) * SP_STR + kf * 8 + tig + 4]);
#pragma unroll
            for (int nf = 0; nf < 16; nf++) {
                unsigned b0 = sV[(kf * 8 + tig) * SV_STR + nf * 8 + gid];
                unsigned b1 = sV[(kf * 8 + tig + 4) * SV_STR + nf * 8 + gid];
                mma8(o[nf], a, b0, b1);
            }
        }
        __syncwarp();
    }

    float L0 = l0 + __shfl_xor_sync(0xffffffffu, l0, 1);
    L0 += __shfl_xor_sync(0xffffffffu, L0, 2);
    float L1 = l1 + __shfl_xor_sync(0xffffffffu, l1, 1);
    L1 += __shfl_xor_sync(0xffffffffu, L1, 2);
    float inv0 = 1.f / L0, inv1 = 1.f / L1;

    float* op  = outp + (size_t)trow * 2048 + h * 128;
    float* op8 = op + 8 * 2048;
#pragma unroll
    for (int nf = 0; nf < 16; nf++) {
        int d = nf * 8 + tig * 2;
        *(float2*)&op[d]  = make_float2(o[nf][0] * inv0, o[nf][1] * inv0);
        *(float2*)&op8[d] = make_float2(o[nf][2] * inv1, o[nf][3] * inv1);
    }
}

// ---------------------------------------------------------------------------
extern "C" void kernel_launch(void* const* d_in, const int* in_sizes, int n_in,
                              void* d_out, int out_size)
{
    const float* und  = (const float*)d_in[0];
    const float* gen  = (const float*)d_in[1];
    // d_in[2], d_in[3]: und/gen token index arrays (arange(0,S,2)/arange(1,S,2) by construction)
    const float* q_w  = (const float*)d_in[4];
    const float* q_b  = (const float*)d_in[5];
    const float* k_w  = (const float*)d_in[6];
    const float* k_b  = (const float*)d_in[7];
    const float* v_w  = (const float*)d_in[8];
    const float* v_b  = (const float*)d_in[9];
    const float* o_w  = (const float*)d_in[10];
    const float* q_wg = (const float*)d_in[11];
    const float* q_bg = (const float*)d_in[12];
    const float* k_wg = (const float*)d_in[13];
    const float* k_bg = (const float*)d_in[14];
    const float* v_wg = (const float*)d_in[15];
    const float* v_bg = (const float*)d_in[16];
    const float* o_wg = (const float*)d_in[17];
    const float* qn   = (const float*)d_in[18];
    const float* kn   = (const float*)d_in[19];
    const float* qng  = (const float*)d_in[20];
    const float* kng  = (const float*)d_in[21];
    const float* cosp = (const float*)d_in[22];
    const float* sinp = (const float*)d_in[23];
    float* out = (float*)d_out;

    float *qkv = nullptr, *att = nullptr;
    cudaGetSymbolAddress((void**)&qkv, g_qkv);
    cudaGetSymbolAddress((void**)&att, g_att);

    dim3 blk(256);

    // QKV projections: und rows -> even tokens (c_off=0), gen rows -> odd (c_off=1)
    gemm_tf32<<<dim3(16, 32), blk>>>(und, 0, 1, q_w,  q_b,  qkv,        3072, 0, 2);
    gemm_tf32<<<dim3(4, 32),  blk>>>(und, 0, 1, k_w,  k_b,  qkv + 2048, 3072, 0, 2);
    gemm_tf32<<<dim3(4, 32),  blk>>>(und, 0, 1, v_w,  v_b,  qkv + 2560, 3072, 0, 2);
    gemm_tf32<<<dim3(16, 32), blk>>>(gen, 0, 1, q_wg, q_bg, qkv,        3072, 1, 2);
    gemm_tf32<<<dim3(4, 32),  blk>>>(gen, 0, 1, k_wg, k_bg, qkv + 2048, 3072, 1, 2);
    gemm_tf32<<<dim3(4, 32),  blk>>>(gen, 0, 1, v_wg, v_bg, qkv + 2560, 3072, 1, 2);

    // RMSNorm + RoPE on q and k heads, in place
    norm_rope<<<20480, 256>>>(qkv, cosp, sinp, qn, qng, kn, kng);

    // Flash attention
    cudaFuncSetAttribute(attn_kernel, cudaFuncAttributeMaxDynamicSharedMemorySize, ATT_SMEM);
    attn_kernel<<<dim3(16, 4, 16), 256, ATT_SMEM>>>(qkv, att);

    // Output projections: even tokens -> out_und, odd -> out_gen
    gemm_tf32<<<dim3(16, 32), blk>>>(att, 0, 2, o_w,  nullptr, out,                2048, 0, 1);
    gemm_tf32<<<dim3(16, 32), blk>>>(att, 1, 2, o_wg, nullptr, out + 4096 * 2048, 2048, 0, 1);
}

// round 4
// speedup vs baseline: 1.1350x; 1.1284x over previous
#include <cuda_runtime.h>
#include <cuda_bf16.h>

// Problem constants
#define S_TOT 8192
#define HID   2048

// Scratch (allocation-free rule: __device__ globals) — all tf32-pre-rounded f32
__device__ float g_qkv [S_TOT * 3072];      // [S][ q(2048) | k(512) | v(512) ]
__device__ float g_att [S_TOT * 2048];      // attention output (rounded)
__device__ float g_in  [S_TOT * 2048];      // rounded inputs: und rows 0..4095, gen 4096..8191
__device__ float g_wqkv[2 * 3072 * 2048];   // fused rounded [qw|kw|vw] und, gen
__device__ float g_wo  [2 * 2048 * 2048];   // rounded o_w und, gen
__device__ float g_bias[2 * 3072];          // fused bias und, gen

__device__ __forceinline__ unsigned f2t(float f) {
    unsigned u;
    asm("cvt.rna.tf32.f32 %0, %1;" : "=r"(u) : "f"(f));
    return u;
}

__device__ __forceinline__ void mma8(float c[4], const unsigned a[4], unsigned b0, unsigned b1) {
    asm volatile(
        "mma.sync.aligned.m16n8k8.row.col.f32.tf32.tf32.f32 "
        "{%0,%1,%2,%3}, {%4,%5,%6,%7}, {%8,%9}, {%0,%1,%2,%3};"
        : "+f"(c[0]), "+f"(c[1]), "+f"(c[2]), "+f"(c[3])
        : "r"(a[0]), "r"(a[1]), "r"(a[2]), "r"(a[3]), "r"(b0), "r"(b1));
}

__device__ __forceinline__ void cp16(unsigned saddr, const void* g) {
    asm volatile("cp.async.cg.shared.global [%0], [%1], 16;\n" :: "r"(saddr), "l"(g));
}

// ---------------------------------------------------------------------------
// Conversion / assembly kernels
// ---------------------------------------------------------------------------
__global__ void round_copy(float* __restrict__ dst, const float* __restrict__ src, int n4) {
    int i = blockIdx.x * blockDim.x + threadIdx.x;
    if (i >= n4) return;
    float4 v = ((const float4*)src)[i];
    ((uint4*)dst)[i] = make_uint4(f2t(v.x), f2t(v.y), f2t(v.z), f2t(v.w));
}

__global__ void assemble_qkv_w(float* __restrict__ dst,
                               const float* __restrict__ qw,
                               const float* __restrict__ kw,
                               const float* __restrict__ vw) {
    int i = blockIdx.x * blockDim.x + threadIdx.x;   // float4 index over 3072x2048
    if (i >= 3072 * 512) return;
    int pos = i * 4;
    int n = pos >> 11, k = pos & 2047;
    const float* src;
    if (n < 2048)      src = qw + (size_t)n * 2048;
    else if (n < 2560) src = kw + (size_t)(n - 2048) * 2048;
    else               src = vw + (size_t)(n - 2560) * 2048;
    float4 v = *(const float4*)(src + k);
    ((uint4*)dst)[i] = make_uint4(f2t(v.x), f2t(v.y), f2t(v.z), f2t(v.w));
}

__global__ void assemble_bias(float* __restrict__ dst,
                              const float* qb,  const float* kb,  const float* vb,
                              const float* qbg, const float* kbg, const float* vbg) {
    int i = blockIdx.x * blockDim.x + threadIdx.x;   // 0..6143
    if (i >= 6144) return;
    bool gsel = i >= 3072;
    int n = gsel ? i - 3072 : i;          // FIX: 3072 is not a power of two; (i & 3071) was wrong
    const float* q = gsel ? qbg : qb;
    const float* k = gsel ? kbg : kb;
    const float* v = gsel ? vbg : vb;
    dst[i] = (n < 2048) ? q[n] : (n < 2560) ? k[n - 2048] : v[n - 2560];
}

// ---------------------------------------------------------------------------
// Pipelined tf32 GEMM (inputs pre-rounded): C[m][n] = sum_k A[row(m)][k]*W[n][k] + bias[n]
// Tile 128x128x32, 8 warps of 64x32, cp.async double buffer.
// ---------------------------------------------------------------------------
#define GEMM_SMEM (2 * 9216 * 4)

__global__ __launch_bounds__(256, 2) void gemm_pipe(
    const float* __restrict__ A, int a_off, int a_stride,
    const float* __restrict__ W, const float* __restrict__ bias,
    float* __restrict__ C, int ldc, int c_off, int c_stride)
{
    extern __shared__ unsigned gsm[];
    const int tid = threadIdx.x;
    const int wid = tid >> 5, lane = tid & 31;
    const int gid = lane >> 2, tig = lane & 3;
    const int wm = (wid >> 2) * 64, wn = (wid & 3) * 32;
    const int bm = blockIdx.y * 128, bn = blockIdx.x * 128;

    const int lrow = tid >> 3;          // 0..31
    const int lcol = (tid & 7) * 4;     // 0..28
    const float* ga[4];
    const float* gw[4];
    unsigned offA[4], offB[4];
#pragma unroll
    for (int i = 0; i < 4; i++) {
        int r = lrow + 32 * i;
        ga[i]   = A + (size_t)(a_off + (bm + r) * a_stride) * 2048 + lcol;
        gw[i]   = W + (size_t)(bn + r) * 2048 + lcol;
        offA[i] = (r * 36 + lcol) * 4;
        offB[i] = (4608 + r * 36 + lcol) * 4;
    }
    const unsigned sbase = (unsigned)__cvta_generic_to_shared(gsm);

    float acc[4][4][4];
#pragma unroll
    for (int i = 0; i < 4; i++)
#pragma unroll
        for (int j = 0; j < 4; j++)
#pragma unroll
            for (int c = 0; c < 4; c++) acc[i][j][c] = 0.f;

    {
        unsigned b = sbase;
#pragma unroll
        for (int i = 0; i < 4; i++) { cp16(b + offA[i], ga[i]); cp16(b + offB[i], gw[i]); }
        asm volatile("cp.async.commit_group;\n" ::);
    }

#pragma unroll 1
    for (int kt = 0; kt < 2048; kt += 32) {
        const int s = (kt >> 5) & 1;
        asm volatile("cp.async.wait_group 0;\n" ::);
        __syncthreads();
        if (kt + 32 < 2048) {
            unsigned b = sbase + (s ^ 1) * 9216 * 4;
            int kn = kt + 32;
#pragma unroll
            for (int i = 0; i < 4; i++) { cp16(b + offA[i], ga[i] + kn); cp16(b + offB[i], gw[i] + kn); }
            asm volatile("cp.async.commit_group;\n" ::);
        }
        const unsigned* sA = gsm + s * 9216;
        const unsigned* sB = sA + 4608;
#pragma unroll
        for (int ks = 0; ks < 4; ks++) {
            unsigned af[4][4], bf[4][2];
#pragma unroll
            for (int mf = 0; mf < 4; mf++) {
                const unsigned* p = &sA[(wm + mf * 16 + gid) * 36 + ks * 8 + tig];
                af[mf][0] = p[0];      af[mf][2] = p[4];
                af[mf][1] = p[8 * 36]; af[mf][3] = p[8 * 36 + 4];
            }
#pragma unroll
            for (int nf = 0; nf < 4; nf++) {
                const unsigned* p = &sB[(wn + nf * 8 + gid) * 36 + ks * 8 + tig];
                bf[nf][0] = p[0]; bf[nf][1] = p[4];
            }
#pragma unroll
            for (int mf = 0; mf < 4; mf++)
#pragma unroll
                for (int nf = 0; nf < 4; nf++)
                    mma8(acc[mf][nf], af[mf], bf[nf][0], bf[nf][1]);
        }
    }

#pragma unroll
    for (int mf = 0; mf < 4; mf++) {
#pragma unroll
        for (int nf = 0; nf < 4; nf++) {
            int gc = bn + wn + nf * 8 + tig * 2;
            float b0 = bias ? bias[gc] : 0.f;
            float b1 = bias ? bias[gc + 1] : 0.f;
            int gr = bm + wm + mf * 16 + gid;
            float2 v0 = make_float2(acc[mf][nf][0] + b0, acc[mf][nf][1] + b1);
            float2 v1 = make_float2(acc[mf][nf][2] + b0, acc[mf][nf][3] + b1);
            *(float2*)&C[(size_t)(c_off + gr * c_stride) * ldc + gc] = v0;
            *(float2*)&C[(size_t)(c_off + (gr + 8) * c_stride) * ldc + gc] = v1;
        }
    }
}

// ---------------------------------------------------------------------------
// Per-head RMSNorm + RoPE, in-place on g_qkv. One warp per (token, head).
// ---------------------------------------------------------------------------
__global__ __launch_bounds__(256) void norm_rope(
    float* __restrict__ qkv,
    const float* __restrict__ cosp, const float* __restrict__ sinp,
    const float* __restrict__ qn, const float* __restrict__ qng,
    const float* __restrict__ kn, const float* __restrict__ kng)
{
    int task = blockIdx.x * 8 + (threadIdx.x >> 5);
    int lane = threadIdx.x & 31;
    int s = task / 20, j = task % 20;
    bool und = (s & 1) == 0;
    const float* w;
    int off;
    if (j < 16) { off = j * 128;               w = und ? qn : qng; }
    else        { off = 2048 + (j - 16) * 128; w = und ? kn : kng; }

    float* p = qkv + (size_t)s * 3072 + off;
    float x0 = p[lane], x1 = p[lane + 32], x2 = p[lane + 64], x3 = p[lane + 96];
    float ss = x0 * x0 + x1 * x1 + x2 * x2 + x3 * x3;
#pragma unroll
    for (int d = 16; d; d >>= 1) ss += __shfl_xor_sync(0xffffffffu, ss, d);
    float r = rsqrtf(ss * (1.0f / 128.0f) + 1e-6f);
    x0 = x0 * r * w[lane];      x1 = x1 * r * w[lane + 32];
    x2 = x2 * r * w[lane + 64]; x3 = x3 * r * w[lane + 96];

    const float* cs = cosp + (size_t)s * 128;
    const float* sn = sinp + (size_t)s * 128;
    float c0 = cs[lane], c1 = cs[lane + 32], c2 = cs[lane + 64], c3 = cs[lane + 96];
    float s0 = sn[lane], s1 = sn[lane + 32], s2 = sn[lane + 64], s3 = sn[lane + 96];

    p[lane]      = x0 * c0 - x2 * s0;
    p[lane + 32] = x1 * c1 - x3 * s1;
    p[lane + 64] = x2 * c2 + x0 * s2;
    p[lane + 96] = x3 * c3 + x1 * s3;
}

// ---------------------------------------------------------------------------
// Causal GQA flash attention (tf32 mma). Block = (b, hkv, 32 q-rows) x G=4 heads.
// ---------------------------------------------------------------------------
#define SK_STR 132
#define SV_STR 136
#define SP_STR 68
#define ATT_SMEM ((64 * SK_STR + 64 * SV_STR + 8 * 16 * SP_STR) * 4)

__global__ __launch_bounds__(256, 1) void attn_kernel(
    const float* __restrict__ qkv, float* __restrict__ outp)
{
    extern __shared__ unsigned sm[];
    unsigned* sK = sm;
    unsigned* sV = sm + 64 * SK_STR;
    float* sP = (float*)(sm + 64 * SK_STR + 64 * SV_STR);

    const int qt = blockIdx.x, hkv = blockIdx.y, b = blockIdx.z;
    const int tid = threadIdx.x, wid = tid >> 5, lane = tid & 31;
    const int gid = lane >> 2, tig = lane & 3;
    const int g = wid >> 1;
    const int h = hkv * 4 + g;
    const int q0 = qt * 32;
    const int qrow = q0 + (wid & 1) * 16 + gid;
    const int trow = b * 512 + qrow;
    const float scale = 0.08838834764831845f;

    unsigned qa[16][4];
    {
        const float* qp  = qkv + (size_t)trow * 3072 + h * 128;
        const float* qp8 = qp + 8 * 3072;
#pragma unroll
        for (int kf = 0; kf < 16; kf++) {
            qa[kf][0] = f2t(qp [kf * 8 + tig]     * scale);
            qa[kf][2] = f2t(qp [kf * 8 + tig + 4] * scale);
            qa[kf][1] = f2t(qp8[kf * 8 + tig]     * scale);
            qa[kf][3] = f2t(qp8[kf * 8 + tig + 4] * scale);
        }
    }

    float o[16][4];
#pragma unroll
    for (int i = 0; i < 16; i++)
#pragma unroll
        for (int c = 0; c < 4; c++) o[i][c] = 0.f;
    float m0 = -1e30f, m1 = -1e30f, l0 = 0.f, l1 = 0.f;
    float* myP = sP + wid * 16 * SP_STR;
    const int ntiles = (q0 >> 6) + 1;

#pragma unroll 1
    for (int j = 0; j < ntiles; j++) {
        int c0 = j * 64;
        __syncthreads();
        {
            const float* kb = qkv + (size_t)(b * 512 + c0) * 3072 + 2048 + hkv * 128;
            const float* vb = kb + 512;
#pragma unroll
            for (int i = 0; i < 8; i++) {
                int r = i * 8 + wid;
                int cc = lane * 4;
                float4 kv = *(const float4*)(kb + (size_t)r * 3072 + cc);
                unsigned* d = &sK[r * SK_STR + cc];
                d[0] = f2t(kv.x); d[1] = f2t(kv.y); d[2] = f2t(kv.z); d[3] = f2t(kv.w);
                float4 vv = *(const float4*)(vb + (size_t)r * 3072 + cc);
                unsigned* e = &sV[r * SV_STR + cc];
                e[0] = f2t(vv.x); e[1] = f2t(vv.y); e[2] = f2t(vv.z); e[3] = f2t(vv.w);
            }
        }
        __syncthreads();

        float s[8][4];
#pragma unroll
        for (int nf = 0; nf < 8; nf++)
#pragma unroll
            for (int c = 0; c < 4; c++) s[nf][c] = 0.f;

#pragma unroll
        for (int kf = 0; kf < 16; kf++) {
#pragma unroll
            for (int nf = 0; nf < 8; nf++) {
                unsigned b0 = sK[(nf * 8 + gid) * SK_STR + kf * 8 + tig];
                unsigned b1 = sK[(nf * 8 + gid) * SK_STR + kf * 8 + tig + 4];
                mma8(s[nf], qa[kf], b0, b1);
            }
        }

        if (j == ntiles - 1) {
#pragma unroll
            for (int nf = 0; nf < 8; nf++) {
                int col = c0 + nf * 8 + tig * 2;
                if (col     > qrow)     s[nf][0] = -1e30f;
                if (col + 1 > qrow)     s[nf][1] = -1e30f;
                if (col     > qrow + 8) s[nf][2] = -1e30f;
                if (col + 1 > qrow + 8) s[nf][3] = -1e30f;
            }
        }

        float mj0 = -1e30f, mj1 = -1e30f;
#pragma unroll
        for (int nf = 0; nf < 8; nf++) {
            mj0 = fmaxf(mj0, fmaxf(s[nf][0], s[nf][1]));
            mj1 = fmaxf(mj1, fmaxf(s[nf][2], s[nf][3]));
        }
        mj0 = fmaxf(mj0, __shfl_xor_sync(0xffffffffu, mj0, 1));
        mj0 = fmaxf(mj0, __shfl_xor_sync(0xffffffffu, mj0, 2));
        mj1 = fmaxf(mj1, __shfl_xor_sync(0xffffffffu, mj1, 1));
        mj1 = fmaxf(mj1, __shfl_xor_sync(0xffffffffu, mj1, 2));

        float mn0 = fmaxf(m0, mj0), mn1 = fmaxf(m1, mj1);
        float f0 = __expf(m0 - mn0), f1 = __expf(m1 - mn1);
        m0 = mn0; m1 = mn1;
        l0 *= f0; l1 *= f1;
#pragma unroll
        for (int nf = 0; nf < 16; nf++) {
            o[nf][0] *= f0; o[nf][1] *= f0;
            o[nf][2] *= f1; o[nf][3] *= f1;
        }
#pragma unroll
        for (int nf = 0; nf < 8; nf++) {
            float p0 = __expf(s[nf][0] - m0), p1 = __expf(s[nf][1] - m0);
            float p2 = __expf(s[nf][2] - m1), p3 = __expf(s[nf][3] - m1);
            l0 += p0 + p1; l1 += p2 + p3;
            *(float2*)&myP[gid * SP_STR + nf * 8 + tig * 2]       = make_float2(p0, p1);
            *(float2*)&myP[(gid + 8) * SP_STR + nf * 8 + tig * 2] = make_float2(p2, p3);
        }
        __syncwarp();
#pragma unroll
        for (int kf = 0; kf < 8; kf++) {
            unsigned a[4];
            a[0] = f2t(myP[gid * SP_STR + kf * 8 + tig]);
            a[2] = f2t(myP[gid * SP_STR + kf * 8 + tig + 4]);
            a[1] = f2t(myP[(gid + 8) * SP_STR + kf * 8 + tig]);
            a[3] = f2t(myP[(gid + 8) * SP_STR + kf * 8 + tig + 4]);
#pragma unroll
            for (int nf = 0; nf < 16; nf++) {
                unsigned b0 = sV[(kf * 8 + tig) * SV_STR + nf * 8 + gid];
                unsigned b1 = sV[(kf * 8 + tig + 4) * SV_STR + nf * 8 + gid];
                mma8(o[nf], a, b0, b1);
            }
        }
        __syncwarp();
    }

    float L0 = l0 + __shfl_xor_sync(0xffffffffu, l0, 1);
    L0 += __shfl_xor_sync(0xffffffffu, L0, 2);
    float L1 = l1 + __shfl_xor_sync(0xffffffffu, l1, 1);
    L1 += __shfl_xor_sync(0xffffffffu, L1, 2);
    float inv0 = 1.f / L0, inv1 = 1.f / L1;

    // store tf32-ROUNDED outputs so the o-projection GEMM can consume directly
    float* op  = outp + (size_t)trow * 2048 + h * 128;
    float* op8 = op + 8 * 2048;
#pragma unroll
    for (int nf = 0; nf < 16; nf++) {
        int d = nf * 8 + tig * 2;
        *(uint2*)&op[d]  = make_uint2(f2t(o[nf][0] * inv0), f2t(o[nf][1] * inv0));
        *(uint2*)&op8[d] = make_uint2(f2t(o[nf][2] * inv1), f2t(o[nf][3] * inv1));
    }
}

// ---------------------------------------------------------------------------
extern "C" void kernel_launch(void* const* d_in, const int* in_sizes, int n_in,
                              void* d_out, int out_size)
{
    const float* und  = (const float*)d_in[0];
    const float* gen  = (const float*)d_in[1];
    const float* q_w  = (const float*)d_in[4];
    const float* q_b  = (const float*)d_in[5];
    const float* k_w  = (const float*)d_in[6];
    const float* k_b  = (const float*)d_in[7];
    const float* v_w  = (const float*)d_in[8];
    const float* v_b  = (const float*)d_in[9];
    const float* o_w  = (const float*)d_in[10];
    const float* q_wg = (const float*)d_in[11];
    const float* q_bg = (const float*)d_in[12];
    const float* k_wg = (const float*)d_in[13];
    const float* k_bg = (const float*)d_in[14];
    const float* v_wg = (const float*)d_in[15];
    const float* v_bg = (const float*)d_in[16];
    const float* o_wg = (const float*)d_in[17];
    const float* qn   = (const float*)d_in[18];
    const float* kn   = (const float*)d_in[19];
    const float* qng  = (const float*)d_in[20];
    const float* kng  = (const float*)d_in[21];
    const float* cosp = (const float*)d_in[22];
    const float* sinp = (const float*)d_in[23];
    float* out = (float*)d_out;

    float *qkv, *att, *inb, *wqkv, *wo, *bias;
    cudaGetSymbolAddress((void**)&qkv,  g_qkv);
    cudaGetSymbolAddress((void**)&att,  g_att);
    cudaGetSymbolAddress((void**)&inb,  g_in);
    cudaGetSymbolAddress((void**)&wqkv, g_wqkv);
    cudaGetSymbolAddress((void**)&wo,   g_wo);
    cudaGetSymbolAddress((void**)&bias, g_bias);

    cudaFuncSetAttribute(gemm_pipe,   cudaFuncAttributeMaxDynamicSharedMemorySize, GEMM_SMEM);
    cudaFuncSetAttribute(attn_kernel, cudaFuncAttributeMaxDynamicSharedMemorySize, ATT_SMEM);

    // Pre-round everything to tf32 (numerics identical to in-GEMM rounding)
    round_copy<<<8192, 256>>>(inb,                 und,  4096 * 512);
    round_copy<<<8192, 256>>>(inb + 4096 * 2048,   gen,  4096 * 512);
    round_copy<<<4096, 256>>>(wo,                  o_w,  2048 * 512);
    round_copy<<<4096, 256>>>(wo + 2048 * 2048,    o_wg, 2048 * 512);
    assemble_qkv_w<<<6144, 256>>>(wqkv,               q_w,  k_w,  v_w);
    assemble_qkv_w<<<6144, 256>>>(wqkv + 3072 * 2048, q_wg, k_wg, v_wg);
    assemble_bias<<<24, 256>>>(bias, q_b, k_b, v_b, q_bg, k_bg, v_bg);

    // Fused QKV projections (N=3072): und rows -> even tokens, gen -> odd
    gemm_pipe<<<dim3(24, 32), 256, GEMM_SMEM>>>(inb,               0, 1, wqkv,               bias,        qkv, 3072, 0, 2);
    gemm_pipe<<<dim3(24, 32), 256, GEMM_SMEM>>>(inb + 4096 * 2048, 0, 1, wqkv + 3072 * 2048, bias + 3072, qkv, 3072, 1, 2);

    // RMSNorm + RoPE
    norm_rope<<<20480, 256>>>(qkv, cosp, sinp, qn, qng, kn, kng);

    // Flash attention (writes rounded output)
    attn_kernel<<<dim3(16, 4, 16), 256, ATT_SMEM>>>(qkv, att);

    // Output projections
    gemm_pipe<<<dim3(16, 32), 256, GEMM_SMEM>>>(att, 0, 2, wo,               nullptr, out,               2048, 0, 1);
    gemm_pipe<<<dim3(16, 32), 256, GEMM_SMEM>>>(att, 1, 2, wo + 2048 * 2048, nullptr, out + 4096 * 2048, 2048, 0, 1);
}

// round 6
// speedup vs baseline: 1.1625x; 1.0242x over previous
#include <cuda_runtime.h>
#include <cuda_bf16.h>

// Problem constants
#define S_TOT 8192
#define HID   2048

// Scratch (allocation-free rule: __device__ globals) — all tf32-pre-rounded f32
__device__ float g_qkv [S_TOT * 3072];      // [S][ q(2048) | k(512) | v(512) ]
__device__ float g_att [S_TOT * 2048];      // attention output (rounded)
__device__ float g_in  [S_TOT * 2048];      // rounded inputs: und rows 0..4095, gen 4096..8191
__device__ float g_wqkv[2 * 3072 * 2048];   // fused rounded [qw|kw|vw] und, gen
__device__ float g_wo  [2 * 2048 * 2048];   // rounded o_w und, gen
__device__ float g_bias[2 * 3072];          // fused bias und, gen

__device__ __forceinline__ unsigned f2t(float f) {
    unsigned u;
    asm("cvt.rna.tf32.f32 %0, %1;" : "=r"(u) : "f"(f));
    return u;
}

__device__ __forceinline__ void mma8(float c[4], const unsigned a[4], unsigned b0, unsigned b1) {
    asm volatile(
        "mma.sync.aligned.m16n8k8.row.col.f32.tf32.tf32.f32 "
        "{%0,%1,%2,%3}, {%4,%5,%6,%7}, {%8,%9}, {%0,%1,%2,%3};"
        : "+f"(c[0]), "+f"(c[1]), "+f"(c[2]), "+f"(c[3])
        : "r"(a[0]), "r"(a[1]), "r"(a[2]), "r"(a[3]), "r"(b0), "r"(b1));
}

__device__ __forceinline__ void cp16(unsigned saddr, const void* g) {
    asm volatile("cp.async.cg.shared.global [%0], [%1], 16;\n" :: "r"(saddr), "l"(g));
}

// ---------------------------------------------------------------------------
// Conversion / assembly kernels
// ---------------------------------------------------------------------------
__global__ void round_copy(float* __restrict__ dst, const float* __restrict__ src, int n4) {
    int i = blockIdx.x * blockDim.x + threadIdx.x;
    if (i >= n4) return;
    float4 v = ((const float4*)src)[i];
    ((uint4*)dst)[i] = make_uint4(f2t(v.x), f2t(v.y), f2t(v.z), f2t(v.w));
}

__global__ void assemble_qkv_w(float* __restrict__ dst,
                               const float* __restrict__ qw,
                               const float* __restrict__ kw,
                               const float* __restrict__ vw) {
    int i = blockIdx.x * blockDim.x + threadIdx.x;   // float4 index over 3072x2048
    if (i >= 3072 * 512) return;
    int pos = i * 4;
    int n = pos >> 11, k = pos & 2047;
    const float* src;
    if (n < 2048)      src = qw + (size_t)n * 2048;
    else if (n < 2560) src = kw + (size_t)(n - 2048) * 2048;
    else               src = vw + (size_t)(n - 2560) * 2048;
    float4 v = *(const float4*)(src + k);
    ((uint4*)dst)[i] = make_uint4(f2t(v.x), f2t(v.y), f2t(v.z), f2t(v.w));
}

__global__ void assemble_bias(float* __restrict__ dst,
                              const float* qb,  const float* kb,  const float* vb,
                              const float* qbg, const float* kbg, const float* vbg) {
    int i = blockIdx.x * blockDim.x + threadIdx.x;   // 0..6143
    if (i >= 6144) return;
    bool gsel = i >= 3072;
    int n = gsel ? i - 3072 : i;          // 3072 not a power of two; explicit subtract
    const float* q = gsel ? qbg : qb;
    const float* k = gsel ? kbg : kb;
    const float* v = gsel ? vbg : vb;
    dst[i] = (n < 2048) ? q[n] : (n < 2560) ? k[n - 2048] : v[n - 2560];
}

// ---------------------------------------------------------------------------
// Pipelined tf32 GEMM: C[m][n] = sum_k A[row(m)][k]*W[n][k] + bias[n]
// CTA tile 256x128x32, 8 warps (4x2) each 64x64, 3-stage cp.async ring.
// Smem stage: A 256x36 + B 128x36 words (stride 36 -> conflict-free frags).
// Grid: (N/128, M/256). A rows: a_off + m*a_stride; C rows: c_off + m*c_stride.
// ---------------------------------------------------------------------------
#define STG_W   13824                       // words per stage: 256*36 + 128*36
#define GEMM_SMEM (3 * STG_W * 4)           // 165,888 B

__global__ __launch_bounds__(256, 1) void gemm_pipe(
    const float* __restrict__ A, int a_off, int a_stride,
    const float* __restrict__ W, const float* __restrict__ bias,
    float* __restrict__ C, int ldc, int c_off, int c_stride)
{
    extern __shared__ unsigned gsm[];
    const int tid = threadIdx.x;
    const int wid = tid >> 5, lane = tid & 31;
    const int gid = lane >> 2, tig = lane & 3;
    const int wm = (wid & 3) * 64, wn = (wid >> 2) * 64;
    const int bm = blockIdx.y * 256, bn = blockIdx.x * 128;

    // loaders: thread moves 8 x 16B for A, 4 x 16B for B per stage
    const int lr  = tid >> 3;           // 0..31
    const int lc  = (tid & 7) * 4;      // 0..28
    const float* ga[8];
    const float* gw[4];
    unsigned offA[8], offB[4];
#pragma unroll
    for (int i = 0; i < 8; i++) {
        int r = lr + 32 * i;            // 0..255
        ga[i]   = A + (size_t)(a_off + (bm + r) * a_stride) * 2048 + lc;
        offA[i] = (r * 36 + lc) * 4;
    }
#pragma unroll
    for (int i = 0; i < 4; i++) {
        int r = lr + 32 * i;            // 0..127
        gw[i]   = W + (size_t)(bn + r) * 2048 + lc;
        offB[i] = (9216 + r * 36 + lc) * 4;
    }
    const unsigned sbase = (unsigned)__cvta_generic_to_shared(gsm);

#define LOADCHUNK(slot, kc) do {                                                \
    unsigned b_ = sbase + (slot) * (STG_W * 4);                                 \
    int kk_ = (kc) * 32;                                                        \
    _Pragma("unroll") for (int i_ = 0; i_ < 8; i_++) cp16(b_ + offA[i_], ga[i_] + kk_); \
    _Pragma("unroll") for (int i_ = 0; i_ < 4; i_++) cp16(b_ + offB[i_], gw[i_] + kk_); \
    asm volatile("cp.async.commit_group;\n" ::);                                \
} while (0)

    float acc[4][8][4];
#pragma unroll
    for (int i = 0; i < 4; i++)
#pragma unroll
        for (int j = 0; j < 8; j++)
#pragma unroll
            for (int c = 0; c < 4; c++) acc[i][j][c] = 0.f;

    LOADCHUNK(0, 0);
    LOADCHUNK(1, 1);

#pragma unroll 1
    for (int c = 0; c < 64; c++) {
        const int slot = c % 3;
        if (c < 63) asm volatile("cp.async.wait_group 1;\n" ::);
        else        asm volatile("cp.async.wait_group 0;\n" ::);
        __syncthreads();
        if (c + 2 < 64) LOADCHUNK((c + 2) % 3, c + 2);

        const unsigned* sA = gsm + slot * STG_W;
        const unsigned* sB = sA + 9216;
#pragma unroll
        for (int ks = 0; ks < 4; ks++) {
            unsigned af[4][4], bf[8][2];
#pragma unroll
            for (int mf = 0; mf < 4; mf++) {
                const unsigned* p = &sA[(wm + mf * 16 + gid) * 36 + ks * 8 + tig];
                af[mf][0] = p[0];      af[mf][2] = p[4];
                af[mf][1] = p[8 * 36]; af[mf][3] = p[8 * 36 + 4];
            }
#pragma unroll
            for (int nf = 0; nf < 8; nf++) {
                const unsigned* p = &sB[(wn + nf * 8 + gid) * 36 + ks * 8 + tig];
                bf[nf][0] = p[0]; bf[nf][1] = p[4];
            }
#pragma unroll
            for (int mf = 0; mf < 4; mf++)
#pragma unroll
                for (int nf = 0; nf < 8; nf++)
                    mma8(acc[mf][nf], af[mf], bf[nf][0], bf[nf][1]);
        }
    }
#undef LOADCHUNK

#pragma unroll
    for (int mf = 0; mf < 4; mf++) {
#pragma unroll
        for (int nf = 0; nf < 8; nf++) {
            int gc = bn + wn + nf * 8 + tig * 2;
            float b0 = bias ? __ldg(bias + gc)     : 0.f;
            float b1 = bias ? __ldg(bias + gc + 1) : 0.f;
            int gr = bm + wm + mf * 16 + gid;
            float2 v0 = make_float2(acc[mf][nf][0] + b0, acc[mf][nf][1] + b1);
            float2 v1 = make_float2(acc[mf][nf][2] + b0, acc[mf][nf][3] + b1);
            *(float2*)&C[(size_t)(c_off + gr * c_stride) * ldc + gc] = v0;
            *(float2*)&C[(size_t)(c_off + (gr + 8) * c_stride) * ldc + gc] = v1;
        }
    }
}

// ---------------------------------------------------------------------------
// Per-head RMSNorm + RoPE, in-place on g_qkv. One warp per (token, head).
// ---------------------------------------------------------------------------
__global__ __launch_bounds__(256) void norm_rope(
    float* __restrict__ qkv,
    const float* __restrict__ cosp, const float* __restrict__ sinp,
    const float* __restrict__ qn, const float* __restrict__ qng,
    const float* __restrict__ kn, const float* __restrict__ kng)
{
    int task = blockIdx.x * 8 + (threadIdx.x >> 5);
    int lane = threadIdx.x & 31;
    int s = task / 20, j = task % 20;
    bool und = (s & 1) == 0;
    const float* w;
    int off;
    if (j < 16) { off = j * 128;               w = und ? qn : qng; }
    else        { off = 2048 + (j - 16) * 128; w = und ? kn : kng; }

    float* p = qkv + (size_t)s * 3072 + off;
    float x0 = p[lane], x1 = p[lane + 32], x2 = p[lane + 64], x3 = p[lane + 96];
    float ss = x0 * x0 + x1 * x1 + x2 * x2 + x3 * x3;
#pragma unroll
    for (int d = 16; d; d >>= 1) ss += __shfl_xor_sync(0xffffffffu, ss, d);
    float r = rsqrtf(ss * (1.0f / 128.0f) + 1e-6f);
    x0 = x0 * r * w[lane];      x1 = x1 * r * w[lane + 32];
    x2 = x2 * r * w[lane + 64]; x3 = x3 * r * w[lane + 96];

    const float* cs = cosp + (size_t)s * 128;
    const float* sn = sinp + (size_t)s * 128;
    float c0 = cs[lane], c1 = cs[lane + 32], c2 = cs[lane + 64], c3 = cs[lane + 96];
    float s0 = sn[lane], s1 = sn[lane + 32], s2 = sn[lane + 64], s3 = sn[lane + 96];

    p[lane]      = x0 * c0 - x2 * s0;
    p[lane + 32] = x1 * c1 - x3 * s1;
    p[lane + 64] = x2 * c2 + x0 * s2;
    p[lane + 96] = x3 * c3 + x1 * s3;
}

// ---------------------------------------------------------------------------
// Causal GQA flash attention (tf32 mma). Block = (b, hkv, 32 q-rows) x G=4 heads.
// ---------------------------------------------------------------------------
#define SK_STR 132
#define SV_STR 136
#define SP_STR 68
#define ATT_SMEM ((64 * SK_STR + 64 * SV_STR + 8 * 16 * SP_STR) * 4)

__global__ __launch_bounds__(256, 1) void attn_kernel(
    const float* __restrict__ qkv, float* __restrict__ outp)
{
    extern __shared__ unsigned sm[];
    unsigned* sK = sm;
    unsigned* sV = sm + 64 * SK_STR;
    float* sP = (float*)(sm + 64 * SK_STR + 64 * SV_STR);

    const int qt = blockIdx.x, hkv = blockIdx.y, b = blockIdx.z;
    const int tid = threadIdx.x, wid = tid >> 5, lane = tid & 31;
    const int gid = lane >> 2, tig = lane & 3;
    const int g = wid >> 1;
    const int h = hkv * 4 + g;
    const int q0 = qt * 32;
    const int qrow = q0 + (wid & 1) * 16 + gid;
    const int trow = b * 512 + qrow;
    const float scale = 0.08838834764831845f;

    unsigned qa[16][4];
    {
        const float* qp  = qkv + (size_t)trow * 3072 + h * 128;
        const float* qp8 = qp + 8 * 3072;
#pragma unroll
        for (int kf = 0; kf < 16; kf++) {
            qa[kf][0] = f2t(qp [kf * 8 + tig]     * scale);
            qa[kf][2] = f2t(qp [kf * 8 + tig + 4] * scale);
            qa[kf][1] = f2t(qp8[kf * 8 + tig]     * scale);
            qa[kf][3] = f2t(qp8[kf * 8 + tig + 4] * scale);
        }
    }

    float o[16][4];
#pragma unroll
    for (int i = 0; i < 16; i++)
#pragma unroll
        for (int c = 0; c < 4; c++) o[i][c] = 0.f;
    float m0 = -1e30f, m1 = -1e30f, l0 = 0.f, l1 = 0.f;
    float* myP = sP + wid * 16 * SP_STR;
    const int ntiles = (q0 >> 6) + 1;

#pragma unroll 1
    for (int j = 0; j < ntiles; j++) {
        int c0 = j * 64;
        __syncthreads();
        {
            const float* kb = qkv + (size_t)(b * 512 + c0) * 3072 + 2048 + hkv * 128;
            const float* vb = kb + 512;
#pragma unroll
            for (int i = 0; i < 8; i++) {
                int r = i * 8 + wid;
                int cc = lane * 4;
                float4 kv = *(const float4*)(kb + (size_t)r * 3072 + cc);
                unsigned* d = &sK[r * SK_STR + cc];
                d[0] = f2t(kv.x); d[1] = f2t(kv.y); d[2] = f2t(kv.z); d[3] = f2t(kv.w);
                float4 vv = *(const float4*)(vb + (size_t)r * 3072 + cc);
                unsigned* e = &sV[r * SV_STR + cc];
                e[0] = f2t(vv.x); e[1] = f2t(vv.y); e[2] = f2t(vv.z); e[3] = f2t(vv.w);
            }
        }
        __syncthreads();

        float s[8][4];
#pragma unroll
        for (int nf = 0; nf < 8; nf++)
#pragma unroll
            for (int c = 0; c < 4; c++) s[nf][c] = 0.f;

#pragma unroll
        for (int kf = 0; kf < 16; kf++) {
#pragma unroll
            for (int nf = 0; nf < 8; nf++) {
                unsigned b0 = sK[(nf * 8 + gid) * SK_STR + kf * 8 + tig];
                unsigned b1 = sK[(nf * 8 + gid) * SK_STR + kf * 8 + tig + 4];
                mma8(s[nf], qa[kf], b0, b1);
            }
        }

        if (j == ntiles - 1) {
#pragma unroll
            for (int nf = 0; nf < 8; nf++) {
                int col = c0 + nf * 8 + tig * 2;
                if (col     > qrow)     s[nf][0] = -1e30f;
                if (col + 1 > qrow)     s[nf][1] = -1e30f;
                if (col     > qrow + 8) s[nf][2] = -1e30f;
                if (col + 1 > qrow + 8) s[nf][3] = -1e30f;
            }
        }

        float mj0 = -1e30f, mj1 = -1e30f;
#pragma unroll
        for (int nf = 0; nf < 8; nf++) {
            mj0 = fmaxf(mj0, fmaxf(s[nf][0], s[nf][1]));
            mj1 = fmaxf(mj1, fmaxf(s[nf][2], s[nf][3]));
        }
        mj0 = fmaxf(mj0, __shfl_xor_sync(0xffffffffu, mj0, 1));
        mj0 = fmaxf(mj0, __shfl_xor_sync(0xffffffffu, mj0, 2));
        mj1 = fmaxf(mj1, __shfl_xor_sync(0xffffffffu, mj1, 1));
        mj1 = fmaxf(mj1, __shfl_xor_sync(0xffffffffu, mj1, 2));

        float mn0 = fmaxf(m0, mj0), mn1 = fmaxf(m1, mj1);
        float f0 = __expf(m0 - mn0), f1 = __expf(m1 - mn1);
        m0 = mn0; m1 = mn1;
        l0 *= f0; l1 *= f1;
#pragma unroll
        for (int nf = 0; nf < 16; nf++) {
            o[nf][0] *= f0; o[nf][1] *= f0;
            o[nf][2] *= f1; o[nf][3] *= f1;
        }
#pragma unroll
        for (int nf = 0; nf < 8; nf++) {
            float p0 = __expf(s[nf][0] - m0), p1 = __expf(s[nf][1] - m0);
            float p2 = __expf(s[nf][2] - m1), p3 = __expf(s[nf][3] - m1);
            l0 += p0 + p1; l1 += p2 + p3;
            *(float2*)&myP[gid * SP_STR + nf * 8 + tig * 2]       = make_float2(p0, p1);
            *(float2*)&myP[(gid + 8) * SP_STR + nf * 8 + tig * 2] = make_float2(p2, p3);
        }
        __syncwarp();
#pragma unroll
        for (int kf = 0; kf < 8; kf++) {
            unsigned a[4];
            a[0] = f2t(myP[gid * SP_STR + kf * 8 + tig]);
            a[2] = f2t(myP[gid * SP_STR + kf * 8 + tig + 4]);
            a[1] = f2t(myP[(gid + 8) * SP_STR + kf * 8 + tig]);
            a[3] = f2t(myP[(gid + 8) * SP_STR + kf * 8 + tig + 4]);
#pragma unroll
            for (int nf = 0; nf < 16; nf++) {
                unsigned b0 = sV[(kf * 8 + tig) * SV_STR + nf * 8 + gid];
                unsigned b1 = sV[(kf * 8 + tig + 4) * SV_STR + nf * 8 + gid];
                mma8(o[nf], a, b0, b1);
            }
        }
        __syncwarp();
    }

    float L0 = l0 + __shfl_xor_sync(0xffffffffu, l0, 1);
    L0 += __shfl_xor_sync(0xffffffffu, L0, 2);
    float L1 = l1 + __shfl_xor_sync(0xffffffffu, l1, 1);
    L1 += __shfl_xor_sync(0xffffffffu, L1, 2);
    float inv0 = 1.f / L0, inv1 = 1.f / L1;

    // store tf32-ROUNDED outputs so the o-projection GEMM can consume directly
    float* op  = outp + (size_t)trow * 2048 + h * 128;
    float* op8 = op + 8 * 2048;
#pragma unroll
    for (int nf = 0; nf < 16; nf++) {
        int d = nf * 8 + tig * 2;
        *(uint2*)&op[d]  = make_uint2(f2t(o[nf][0] * inv0), f2t(o[nf][1] * inv0));
        *(uint2*)&op8[d] = make_uint2(f2t(o[nf][2] * inv1), f2t(o[nf][3] * inv1));
    }
}

// ---------------------------------------------------------------------------
extern "C" void kernel_launch(void* const* d_in, const int* in_sizes, int n_in,
                              void* d_out, int out_size)
{
    const float* und  = (const float*)d_in[0];
    const float* gen  = (const float*)d_in[1];
    const float* q_w  = (const float*)d_in[4];
    const float* q_b  = (const float*)d_in[5];
    const float* k_w  = (const float*)d_in[6];
    const float* k_b  = (const float*)d_in[7];
    const float* v_w  = (const float*)d_in[8];
    const float* v_b  = (const float*)d_in[9];
    const float* o_w  = (const float*)d_in[10];
    const float* q_wg = (const float*)d_in[11];
    const float* q_bg = (const float*)d_in[12];
    const float* k_wg = (const float*)d_in[13];
    const float* k_bg = (const float*)d_in[14];
    const float* v_wg = (const float*)d_in[15];
    const float* v_bg = (const float*)d_in[16];
    const float* o_wg = (const float*)d_in[17];
    const float* qn   = (const float*)d_in[18];
    const float* kn   = (const float*)d_in[19];
    const float* qng  = (const float*)d_in[20];
    const float* kng  = (const float*)d_in[21];
    const float* cosp = (const float*)d_in[22];
    const float* sinp = (const float*)d_in[23];
    float* out = (float*)d_out;

    float *qkv, *att, *inb, *wqkv, *wo, *bias;
    cudaGetSymbolAddress((void**)&qkv,  g_qkv);
    cudaGetSymbolAddress((void**)&att,  g_att);
    cudaGetSymbolAddress((void**)&inb,  g_in);
    cudaGetSymbolAddress((void**)&wqkv, g_wqkv);
    cudaGetSymbolAddress((void**)&wo,   g_wo);
    cudaGetSymbolAddress((void**)&bias, g_bias);

    cudaFuncSetAttribute(gemm_pipe,   cudaFuncAttributeMaxDynamicSharedMemorySize, GEMM_SMEM);
    cudaFuncSetAttribute(attn_kernel, cudaFuncAttributeMaxDynamicSharedMemorySize, ATT_SMEM);

    // Pre-round everything to tf32 (numerics identical to in-GEMM rounding)
    round_copy<<<8192, 256>>>(inb,                 und,  4096 * 512);
    round_copy<<<8192, 256>>>(inb + 4096 * 2048,   gen,  4096 * 512);
    round_copy<<<4096, 256>>>(wo,                  o_w,  2048 * 512);
    round_copy<<<4096, 256>>>(wo + 2048 * 2048,    o_wg, 2048 * 512);
    assemble_qkv_w<<<6144, 256>>>(wqkv,               q_w,  k_w,  v_w);
    assemble_qkv_w<<<6144, 256>>>(wqkv + 3072 * 2048, q_wg, k_wg, v_wg);
    assemble_bias<<<24, 256>>>(bias, q_b, k_b, v_b, q_bg, k_bg, v_bg);

    // Fused QKV projections (N=3072, M=4096): und -> even tokens, gen -> odd
    gemm_pipe<<<dim3(24, 16), 256, GEMM_SMEM>>>(inb,               0, 1, wqkv,               bias,        qkv, 3072, 0, 2);
    gemm_pipe<<<dim3(24, 16), 256, GEMM_SMEM>>>(inb + 4096 * 2048, 0, 1, wqkv + 3072 * 2048, bias + 3072, qkv, 3072, 1, 2);

    // RMSNorm + RoPE
    norm_rope<<<20480, 256>>>(qkv, cosp, sinp, qn, qng, kn, kng);

    // Flash attention (writes rounded output)
    attn_kernel<<<dim3(16, 4, 16), 256, ATT_SMEM>>>(qkv, att);

    // Output projections (N=2048, M=4096)
    gemm_pipe<<<dim3(16, 16), 256, GEMM_SMEM>>>(att, 0, 2, wo,               nullptr, out,               2048, 0, 1);
    gemm_pipe<<<dim3(16, 16), 256, GEMM_SMEM>>>(att, 1, 2, wo + 2048 * 2048, nullptr, out + 4096 * 2048, 2048, 0, 1);
}